// round 4
// baseline (speedup 1.0000x reference)
#include <cuda_runtime.h>

// MSELoss: out[0] = mean((yhat - y)^2) over 16384*4096 fp32 elements.
// HBM-bound streaming reduction. Two-stage for determinism:
//   stage 1: grid-stride float4 squared-diff sums -> per-block partials
//   stage 2: single block reduces partials, scales by 1/N, writes d_out.

#define NBLOCKS   1184     // 148 SMs * 8 CTAs
#define NTHREADS  256
#define N_ELEMS   67108864LL   // 16384 * 4096
#define N_VEC4    16777216u    // N_ELEMS / 4

__device__ float g_partials[NBLOCKS];

__device__ __forceinline__ float block_reduce(float v) {
    __shared__ float warp_sums[NTHREADS / 32];
    #pragma unroll
    for (int off = 16; off > 0; off >>= 1)
        v += __shfl_down_sync(0xFFFFFFFFu, v, off);
    int lane = threadIdx.x & 31;
    int wid  = threadIdx.x >> 5;
    if (lane == 0) warp_sums[wid] = v;
    __syncthreads();
    if (wid == 0) {
        v = (lane < NTHREADS / 32) ? warp_sums[lane] : 0.0f;
        #pragma unroll
        for (int off = 16; off > 0; off >>= 1)
            v += __shfl_down_sync(0xFFFFFFFFu, v, off);
    }
    return v;  // valid in (wid==0, lane==0)
}

__device__ __forceinline__ float sqdiff4(float4 a, float4 b, float acc) {
    float d0 = a.x - b.x, d1 = a.y - b.y;
    float d2 = a.z - b.z, d3 = a.w - b.w;
    acc = fmaf(d0, d0, acc); acc = fmaf(d1, d1, acc);
    acc = fmaf(d2, d2, acc); acc = fmaf(d3, d3, acc);
    return acc;
}

__global__ __launch_bounds__(NTHREADS) void mse_partial_kernel(
    const float4* __restrict__ yhat,
    const float4* __restrict__ y)
{
    float acc = 0.0f;
    const unsigned stride = NBLOCKS * NTHREADS;
    unsigned i = blockIdx.x * NTHREADS + threadIdx.x;

    // 4-deep unroll: 8 independent LDG.128 batched at loop front (MLP_p1 = 8)
    for (; i + 3u * stride < N_VEC4; i += 4u * stride) {
        float4 a0 = yhat[i];
        float4 b0 = y[i];
        float4 a1 = yhat[i + stride];
        float4 b1 = y[i + stride];
        float4 a2 = yhat[i + 2u * stride];
        float4 b2 = y[i + 2u * stride];
        float4 a3 = yhat[i + 3u * stride];
        float4 b3 = y[i + 3u * stride];
        acc = sqdiff4(a0, b0, acc);
        acc = sqdiff4(a1, b1, acc);
        acc = sqdiff4(a2, b2, acc);
        acc = sqdiff4(a3, b3, acc);
    }
    // tail: up to 3 remaining stride-chunks
    for (; i < N_VEC4; i += stride) {
        float4 a = yhat[i];
        float4 b = y[i];
        acc = sqdiff4(a, b, acc);
    }

    float bsum = block_reduce(acc);
    if (threadIdx.x == 0)
        g_partials[blockIdx.x] = bsum;
}

__global__ __launch_bounds__(NTHREADS) void mse_final_kernel(float* __restrict__ out)
{
    float acc = 0.0f;
    for (int i = threadIdx.x; i < NBLOCKS; i += NTHREADS)
        acc += g_partials[i];
    float total = block_reduce(acc);
    if (threadIdx.x == 0)
        out[0] = total * (1.0f / (float)N_ELEMS);
}

extern "C" void kernel_launch(void* const* d_in, const int* in_sizes, int n_in,
                              void* d_out, int out_size)
{
    const float4* yhat = (const float4*)d_in[0];
    const float4* y    = (const float4*)d_in[1];
    float* out = (float*)d_out;

    mse_partial_kernel<<<NBLOCKS, NTHREADS>>>(yhat, y);
    mse_final_kernel<<<1, NTHREADS>>>(out);
}